// round 1
// baseline (speedup 1.0000x reference)
#include <cuda_runtime.h>
#include <math.h>

// ---------------- scratch (device globals; no allocation) ----------------
__device__ float g_L [2u*4096u*1024u];   // local (sliding window) result, tri-weighted then normalized
__device__ float g_G [2u*4096u*1024u];   // global attention result
__device__ float g_BC[2u*4096u*1024u];   // broadcast diffusion result
__device__ float g_M [2u*4096u*1024u];   // mixed
__device__ float g_COMP[2u*64u*1024u];   // conv output (first 64 tokens), bias included

// =====================================================================
// 1) broadcast diffusion: 12 roll steps fully in shared memory
//    block = (b, 4 consecutive d), 512 threads, smem = 2 x 4096 x 4 floats
// =====================================================================
__global__ void bc_kernel(const float* __restrict__ x, float* __restrict__ bc) {
    extern __shared__ float sm[];
    float* bufA = sm;            // 16384 floats
    float* bufB = sm + 16384;
    const int tid = threadIdx.x;         // 512
    const int b   = blockIdx.y;
    const int d0  = blockIdx.x << 2;
    const float* src = x + (size_t)b * 4194304u + d0;

    for (int s = tid; s < 4096; s += 512)
        *(float4*)&bufA[s << 2] = *(const float4*)(src + (size_t)s * 1024u);
    __syncthreads();

    float acc[32];
#pragma unroll
    for (int e = 0; e < 32; ++e) acc[e] = 0.f;

    float* cur = bufA; float* nxt = bufB;
    for (int st = 1; st < 4096; st <<= 1) {
#pragma unroll
        for (int q = 0; q < 8; ++q) {
            int s   = tid + (q << 9);
            int sc  = s << 2;
            int sm1 = ((s - st) & 4095) << 2;
            int sp1 = ((s + st) & 4095) << 2;
#pragma unroll
            for (int j = 0; j < 4; ++j) {
                float v = cur[sc + j] + 0.5f * (cur[sm1 + j] + cur[sp1 + j]);
                nxt[sc + j] = v;
                acc[(q << 2) + j] += v;
            }
        }
        __syncthreads();
        float* t = cur; cur = nxt; nxt = t;
    }
    const float inv = 1.0f / 13.0f;   // log2(4096)+1
    float* dst = bc + (size_t)b * 4194304u + d0;
#pragma unroll
    for (int q = 0; q < 8; ++q) {
        int s = tid + (q << 9);
        float4 o = make_float4(acc[q*4]*inv, acc[q*4+1]*inv, acc[q*4+2]*inv, acc[q*4+3]*inv);
        *(float4*)(dst + (size_t)s * 1024u) = o;
    }
}

// =====================================================================
// 2) conv1d(k=4, stride=4), only first 64 output tokens needed.
//    GEMM: (m = b*64+t : 128 rows) x (o : 1024) over K = 4096 (= d*4+k)
//    grid 64 blocks (o-tiles of 16), 256 threads, micro 4m x 2o.
// =====================================================================
__global__ void __launch_bounds__(256) conv_kernel(
        const float* __restrict__ x, const float* __restrict__ cw,
        const float* __restrict__ cb, float* __restrict__ comp) {
    __shared__ float As[32 * 129];
    __shared__ float Ws[32 * 20];
    const int tid = threadIdx.x;
    const int o0  = blockIdx.x << 4;
    const int mb  = (tid & 31) << 2;      // 4 m rows
    const int og  = (tid >> 5) << 1;      // 2 o columns

    float acc[4][2];
#pragma unroll
    for (int r = 0; r < 4; ++r) { acc[r][0] = 0.f; acc[r][1] = 0.f; }

    for (int k0 = 0; k0 < 4096; k0 += 32) {
        __syncthreads();
#pragma unroll
        for (int it = 0; it < 16; ++it) {
            int idx = tid + (it << 8);     // 0..4095
            int m   = idx & 127;
            int kc  = idx >> 7;            // 0..31
            int k   = k0 + kc;
            int bb  = m >> 6, t = m & 63;
            As[kc * 129 + m] =
                x[(size_t)bb * 4194304u + (size_t)((t << 2) + (k & 3)) * 1024u + (k >> 2)];
        }
#pragma unroll
        for (int it = 0; it < 2; ++it) {
            int idx = tid + (it << 8);     // 0..511
            int oo = idx >> 5, kc = idx & 31;
            Ws[kc * 20 + oo] = cw[(size_t)(o0 + oo) * 4096u + k0 + kc];
        }
        __syncthreads();
#pragma unroll
        for (int kc = 0; kc < 32; ++kc) {
            float a0 = As[kc*129 + mb + 0];
            float a1 = As[kc*129 + mb + 1];
            float a2 = As[kc*129 + mb + 2];
            float a3 = As[kc*129 + mb + 3];
            float w0 = Ws[kc*20 + og];
            float w1 = Ws[kc*20 + og + 1];
            acc[0][0] += a0*w0; acc[0][1] += a0*w1;
            acc[1][0] += a1*w0; acc[1][1] += a1*w1;
            acc[2][0] += a2*w0; acc[2][1] += a2*w1;
            acc[3][0] += a3*w0; acc[3][1] += a3*w1;
        }
    }
#pragma unroll
    for (int r = 0; r < 4; ++r)
#pragma unroll
        for (int c = 0; c < 2; ++c) {
            int m = mb + r, o = o0 + og + c;
            comp[(size_t)m * 1024u + o] = acc[r][c] + cb[o];
        }
}

// =====================================================================
// 3) sliding-window self-attention (flash style).
//    block = (b, h, window n, q-tile of 64). 256 threads.
//    parity 0 (even windows, disjoint, cover all S): direct store.
//    parity 1 (odd windows, disjoint): accumulate (+=).
//    Contribution is tri-weighted; normalization by den(s) is a later pass.
// =====================================================================
__global__ void __launch_bounds__(256) win_attn(
        const float* __restrict__ x, float* __restrict__ L, int parity) {
    extern __shared__ float sm[];
    float* Qs = sm;              // 64 x 129
    float* Ks = sm + 8256;       // 64 x 129
    float* Ss = sm + 16512;      // 64 x 65

    const int tid  = threadIdx.x;
    const int qt   = blockIdx.x;                 // 0..7
    const int n    = (blockIdx.y << 1) + parity; // window id
    const int b    = blockIdx.z >> 3, h = blockIdx.z & 7;
    const int base = n << 8;                     // n*256
    const int q0   = base + (qt << 6);
    const float* xb = x + (size_t)b * 4194304u + (h << 7);

#pragma unroll
    for (int it = 0; it < 8; ++it) {
        int i = tid + (it << 8);
        int r = i >> 5, c4 = (i & 31) << 2;
        float4 v = *(const float4*)(xb + (size_t)(q0 + r) * 1024u + c4);
        float* q = &Qs[r * 129 + c4];
        q[0] = v.x; q[1] = v.y; q[2] = v.z; q[3] = v.w;
    }

    const int row  = tid >> 2;
    const int dcol = (tid & 3) << 5;
    const int qb   = (tid >> 4) << 2;
    const int kb   = (tid & 15) << 2;
    const float scale = 0.08838834764831845f;   // 1/sqrt(128)

    float acc[32];
#pragma unroll
    for (int c = 0; c < 32; ++c) acc[c] = 0.f;
    float m_i = -1e30f, l_i = 0.f;

    for (int kt = 0; kt < 8; ++kt) {
        __syncthreads();
        int k0 = base + (kt << 6);
#pragma unroll
        for (int it = 0; it < 8; ++it) {
            int i = tid + (it << 8);
            int r = i >> 5, c4 = (i & 31) << 2;
            float4 v = *(const float4*)(xb + (size_t)(k0 + r) * 1024u + c4);
            float* k = &Ks[r * 129 + c4];
            k[0] = v.x; k[1] = v.y; k[2] = v.z; k[3] = v.w;
        }
        __syncthreads();

        float s4[4][4];
#pragma unroll
        for (int r = 0; r < 4; ++r)
#pragma unroll
            for (int c = 0; c < 4; ++c) s4[r][c] = 0.f;

#pragma unroll 4
        for (int d = 0; d < 128; ++d) {
            float qv[4], kv[4];
#pragma unroll
            for (int r = 0; r < 4; ++r) qv[r] = Qs[(qb + r) * 129 + d];
#pragma unroll
            for (int c = 0; c < 4; ++c) kv[c] = Ks[(kb + c) * 129 + d];
#pragma unroll
            for (int r = 0; r < 4; ++r)
#pragma unroll
                for (int c = 0; c < 4; ++c) s4[r][c] += qv[r] * kv[c];
        }
#pragma unroll
        for (int r = 0; r < 4; ++r)
#pragma unroll
            for (int c = 0; c < 4; ++c)
                Ss[(qb + r) * 65 + kb + c] = s4[r][c] * scale;
        __syncthreads();

        // online softmax (4 threads share one row)
        float mt = -1e30f;
        const int cb0 = (tid & 3) << 4;
#pragma unroll
        for (int jj = 0; jj < 16; ++jj) mt = fmaxf(mt, Ss[row * 65 + cb0 + jj]);
        mt = fmaxf(mt, __shfl_xor_sync(0xffffffffu, mt, 1));
        mt = fmaxf(mt, __shfl_xor_sync(0xffffffffu, mt, 2));
        float m_new = fmaxf(m_i, mt);
        float alpha = __expf(m_i - m_new);
#pragma unroll
        for (int c = 0; c < 32; ++c) acc[c] *= alpha;

        float lsum = 0.f;
        const float* srow = &Ss[row * 65];
#pragma unroll 4
        for (int j = 0; j < 64; ++j) {
            float p = __expf(srow[j] - m_new);
            lsum += p;
            const float* vr = &Ks[j * 129 + dcol];
#pragma unroll
            for (int c = 0; c < 32; ++c) acc[c] += p * vr[c];
        }
        l_i = l_i * alpha + lsum;
        m_i = m_new;
    }

    const float tw = (0.5f + (float)((qt << 6) + row) * (1.0f / 511.0f)) / l_i;
    float* dst = L + ((size_t)b * 4096u + q0 + row) * 1024u + (h << 7) + dcol;
    if (parity == 0) {
#pragma unroll
        for (int c = 0; c < 32; c += 4) {
            float4 o = make_float4(acc[c]*tw, acc[c+1]*tw, acc[c+2]*tw, acc[c+3]*tw);
            *(float4*)(dst + c) = o;
        }
    } else {
#pragma unroll
        for (int c = 0; c < 32; c += 4) {
            float4 o = *(float4*)(dst + c);
            o.x += acc[c]*tw; o.y += acc[c+1]*tw; o.z += acc[c+2]*tw; o.w += acc[c+3]*tw;
            *(float4*)(dst + c) = o;
        }
    }
}

// analytic overlap-add denominator
__device__ __forceinline__ float invden(int s) {
    int n1 = s >> 8, i1 = s & 255;
    float d = 0.f;
    if (n1 <= 14) d += 0.5f + (float)i1 * (1.0f / 511.0f);
    if (n1 >= 1)  d += 0.5f + (float)(i1 + 256) * (1.0f / 511.0f);
    return 1.0f / d;
}

__global__ void norm_local(float* __restrict__ L) {
    size_t i = (size_t)blockIdx.x * blockDim.x + threadIdx.x;   // float4 index
    int s = (int)((i >> 8) & 4095);
    float inv = invden(s);
    float4* p = (float4*)L;
    float4 v = p[i];
    v.x *= inv; v.y *= inv; v.z *= inv; v.w *= inv;
    p[i] = v;
}

// =====================================================================
// 4) compressed-global attention: per (b,h), KV = 128 tokens x 128d in smem.
//    block = (b, h, 32 queries). 256 threads.
// =====================================================================
__global__ void __launch_bounds__(256) gattn(
        const float* __restrict__ x, const float* __restrict__ gmem,
        const float* __restrict__ comp, float* __restrict__ G) {
    extern __shared__ float sm[];
    float* KVs = sm;                 // 128 x 129
    float* Qs  = sm + 16512;         // 32 x 129
    float* Ps  = sm + 20640;         // 32 x 129

    const int tid = threadIdx.x;
    const int s0  = blockIdx.x << 5;
    const int h   = blockIdx.y, b = blockIdx.z;

#pragma unroll
    for (int it = 0; it < 16; ++it) {
        int i = tid + (it << 8);
        int r = i >> 5, c4 = (i & 31) << 2;
        float4 v;
        if (r < 64) v = *(const float4*)(comp + (size_t)((b << 6) + r) * 1024u + (h << 7) + c4);
        else        v = *(const float4*)(gmem + (size_t)((h << 6) + (r - 64)) * 128u + c4);
        float* kv = &KVs[r * 129 + c4];
        kv[0] = v.x; kv[1] = v.y; kv[2] = v.z; kv[3] = v.w;
    }
#pragma unroll
    for (int it = 0; it < 4; ++it) {
        int i = tid + (it << 8);
        int r = i >> 5, c4 = (i & 31) << 2;
        float4 v = *(const float4*)(x + (size_t)b * 4194304u + (size_t)(s0 + r) * 1024u + (h << 7) + c4);
        float* q = &Qs[r * 129 + c4];
        q[0] = v.x; q[1] = v.y; q[2] = v.z; q[3] = v.w;
    }
    __syncthreads();

    // scores: 32q x 128t, 4x4 micro
    {
        const int qb = (tid & 7) << 2;
        const int tb = (tid >> 3) << 2;
        float s4[4][4];
#pragma unroll
        for (int r = 0; r < 4; ++r)
#pragma unroll
            for (int c = 0; c < 4; ++c) s4[r][c] = 0.f;
#pragma unroll 4
        for (int d = 0; d < 128; ++d) {
            float qv[4], kv[4];
#pragma unroll
            for (int r = 0; r < 4; ++r) qv[r] = Qs[(qb + r) * 129 + d];
#pragma unroll
            for (int c = 0; c < 4; ++c) kv[c] = KVs[(tb + c) * 129 + d];
#pragma unroll
            for (int r = 0; r < 4; ++r)
#pragma unroll
                for (int c = 0; c < 4; ++c) s4[r][c] += qv[r] * kv[c];
        }
        const float scale = 0.08838834764831845f;
#pragma unroll
        for (int r = 0; r < 4; ++r)
#pragma unroll
            for (int c = 0; c < 4; ++c)
                Ps[(qb + r) * 129 + tb + c] = s4[r][c] * scale;
    }
    __syncthreads();

    // softmax: 8 warps x 4 rows, 8 lanes per row
    {
        int lane = tid & 31, wid = tid >> 5;
        int row = (wid << 2) + (lane >> 3);
        int c0  = (lane & 7) << 4;
        float* pr = &Ps[row * 129 + c0];
        float mt = -1e30f;
        float pv[16];
#pragma unroll
        for (int jj = 0; jj < 16; ++jj) mt = fmaxf(mt, pr[jj]);
        mt = fmaxf(mt, __shfl_xor_sync(0xffffffffu, mt, 1));
        mt = fmaxf(mt, __shfl_xor_sync(0xffffffffu, mt, 2));
        mt = fmaxf(mt, __shfl_xor_sync(0xffffffffu, mt, 4));
        float ssum = 0.f;
#pragma unroll
        for (int jj = 0; jj < 16; ++jj) { pv[jj] = __expf(pr[jj] - mt); ssum += pv[jj]; }
        ssum += __shfl_xor_sync(0xffffffffu, ssum, 1);
        ssum += __shfl_xor_sync(0xffffffffu, ssum, 2);
        ssum += __shfl_xor_sync(0xffffffffu, ssum, 4);
        float invs = 1.0f / ssum;
#pragma unroll
        for (int jj = 0; jj < 16; ++jj) pr[jj] = pv[jj] * invs;
    }
    __syncthreads();

    // out: 32q x 128d
    {
        const int qg = (tid & 7) << 2;
        const int dg = (tid >> 3) << 2;
        float o4[4][4];
#pragma unroll
        for (int r = 0; r < 4; ++r)
#pragma unroll
            for (int c = 0; c < 4; ++c) o4[r][c] = 0.f;
#pragma unroll 4
        for (int t = 0; t < 128; ++t) {
            float pv[4], kv[4];
#pragma unroll
            for (int r = 0; r < 4; ++r) pv[r] = Ps[(qg + r) * 129 + t];
#pragma unroll
            for (int c = 0; c < 4; ++c) kv[c] = KVs[t * 129 + dg + c];
#pragma unroll
            for (int r = 0; r < 4; ++r)
#pragma unroll
                for (int c = 0; c < 4; ++c) o4[r][c] += pv[r] * kv[c];
        }
#pragma unroll
        for (int r = 0; r < 4; ++r) {
            float4 o = make_float4(o4[r][0], o4[r][1], o4[r][2], o4[r][3]);
            *(float4*)(G + ((size_t)b * 4096u + s0 + qg + r) * 1024u + (h << 7) + dg) = o;
        }
    }
}

// =====================================================================
// 5) mix GEMM: Z = [L/den, G] @ mix_w + mix_b; M = sig(Z)*L + (1-sig)*G + BC
//    128x128 tile, 8x8 micro, 256 threads, K = 2048
// =====================================================================
__global__ void __launch_bounds__(256) gemm_mix(
        const float* __restrict__ Lp, const float* __restrict__ Gp,
        const float* __restrict__ BCp, const float* __restrict__ W,
        const float* __restrict__ mbias, float* __restrict__ Mout) {
    __shared__ float As[16 * 132];
    __shared__ float Bs[16 * 132];
    const int tid = threadIdx.x;
    const int m0  = blockIdx.x << 7;
    const int n0  = blockIdx.y << 7;
    const int am  = tid >> 1;
    const int ak  = (tid & 1) << 3;
    const int bk  = tid >> 4;
    const int bn  = (tid & 15) << 3;
    const int ty  = tid >> 4, tx = tid & 15;

    float acc[8][8];
#pragma unroll
    for (int r = 0; r < 8; ++r)
#pragma unroll
        for (int c = 0; c < 8; ++c) acc[r][c] = 0.f;

    float4 pa0, pa1, pb0, pb1;
    auto fetch = [&](int k0) {
        int k = k0 + ak;
        const float* src = (k < 1024)
            ? (Lp + (size_t)(m0 + am) * 1024u + k)
            : (Gp + (size_t)(m0 + am) * 1024u + (k - 1024));
        pa0 = *(const float4*)src;
        pa1 = *(const float4*)(src + 4);
        const float* bsrc = W + (size_t)(k0 + bk) * 1024u + n0 + bn;
        pb0 = *(const float4*)bsrc;
        pb1 = *(const float4*)(bsrc + 4);
    };
    fetch(0);
    for (int k0 = 0; k0 < 2048; k0 += 16) {
        As[(ak+0)*132 + am] = pa0.x; As[(ak+1)*132 + am] = pa0.y;
        As[(ak+2)*132 + am] = pa0.z; As[(ak+3)*132 + am] = pa0.w;
        As[(ak+4)*132 + am] = pa1.x; As[(ak+5)*132 + am] = pa1.y;
        As[(ak+6)*132 + am] = pa1.z; As[(ak+7)*132 + am] = pa1.w;
        *(float4*)&Bs[bk*132 + bn]     = pb0;
        *(float4*)&Bs[bk*132 + bn + 4] = pb1;
        __syncthreads();
        if (k0 + 16 < 2048) fetch(k0 + 16);
#pragma unroll
        for (int kk = 0; kk < 16; ++kk) {
            float4 a0 = *(float4*)&As[kk*132 + (ty << 3)];
            float4 a1 = *(float4*)&As[kk*132 + (ty << 3) + 4];
            float4 b0 = *(float4*)&Bs[kk*132 + (tx << 3)];
            float4 b1 = *(float4*)&Bs[kk*132 + (tx << 3) + 4];
            float av[8] = {a0.x,a0.y,a0.z,a0.w,a1.x,a1.y,a1.z,a1.w};
            float bv[8] = {b0.x,b0.y,b0.z,b0.w,b1.x,b1.y,b1.z,b1.w};
#pragma unroll
            for (int r = 0; r < 8; ++r)
#pragma unroll
                for (int c = 0; c < 8; ++c) acc[r][c] += av[r] * bv[c];
        }
        __syncthreads();
    }
#pragma unroll
    for (int r = 0; r < 8; ++r) {
        int m = m0 + (ty << 3) + r;
        size_t base = (size_t)m * 1024u + n0 + (tx << 3);
#pragma unroll
        for (int c = 0; c < 8; ++c) {
            int nn = n0 + (tx << 3) + c;
            float z = acc[r][c] + mbias[nn];
            float gate = 1.0f / (1.0f + __expf(-z));
            float lv = Lp[base + c], gv = Gp[base + c], bv = BCp[base + c];
            Mout[base + c] = gate * lv + (1.0f - gate) * gv + bv;
        }
    }
}

// =====================================================================
// 6) out GEMM: OUT = M @ out_w + out_b, K = 1024
// =====================================================================
__global__ void __launch_bounds__(256) gemm_out(
        const float* __restrict__ A, const float* __restrict__ W,
        const float* __restrict__ obias, float* __restrict__ OUT) {
    __shared__ float As[16 * 132];
    __shared__ float Bs[16 * 132];
    const int tid = threadIdx.x;
    const int m0  = blockIdx.x << 7;
    const int n0  = blockIdx.y << 7;
    const int am  = tid >> 1;
    const int ak  = (tid & 1) << 3;
    const int bk  = tid >> 4;
    const int bn  = (tid & 15) << 3;
    const int ty  = tid >> 4, tx = tid & 15;

    float acc[8][8];
#pragma unroll
    for (int r = 0; r < 8; ++r)
#pragma unroll
        for (int c = 0; c < 8; ++c) acc[r][c] = 0.f;

    float4 pa0, pa1, pb0, pb1;
    auto fetch = [&](int k0) {
        const float* src = A + (size_t)(m0 + am) * 1024u + k0 + ak;
        pa0 = *(const float4*)src;
        pa1 = *(const float4*)(src + 4);
        const float* bsrc = W + (size_t)(k0 + bk) * 1024u + n0 + bn;
        pb0 = *(const float4*)bsrc;
        pb1 = *(const float4*)(bsrc + 4);
    };
    fetch(0);
    for (int k0 = 0; k0 < 1024; k0 += 16) {
        As[(ak+0)*132 + am] = pa0.x; As[(ak+1)*132 + am] = pa0.y;
        As[(ak+2)*132 + am] = pa0.z; As[(ak+3)*132 + am] = pa0.w;
        As[(ak+4)*132 + am] = pa1.x; As[(ak+5)*132 + am] = pa1.y;
        As[(ak+6)*132 + am] = pa1.z; As[(ak+7)*132 + am] = pa1.w;
        *(float4*)&Bs[bk*132 + bn]     = pb0;
        *(float4*)&Bs[bk*132 + bn + 4] = pb1;
        __syncthreads();
        if (k0 + 16 < 1024) fetch(k0 + 16);
#pragma unroll
        for (int kk = 0; kk < 16; ++kk) {
            float4 a0 = *(float4*)&As[kk*132 + (ty << 3)];
            float4 a1 = *(float4*)&As[kk*132 + (ty << 3) + 4];
            float4 b0 = *(float4*)&Bs[kk*132 + (tx << 3)];
            float4 b1 = *(float4*)&Bs[kk*132 + (tx << 3) + 4];
            float av[8] = {a0.x,a0.y,a0.z,a0.w,a1.x,a1.y,a1.z,a1.w};
            float bv[8] = {b0.x,b0.y,b0.z,b0.w,b1.x,b1.y,b1.z,b1.w};
#pragma unroll
            for (int r = 0; r < 8; ++r)
#pragma unroll
                for (int c = 0; c < 8; ++c) acc[r][c] += av[r] * bv[c];
        }
        __syncthreads();
    }
#pragma unroll
    for (int r = 0; r < 8; ++r) {
        int m = m0 + (ty << 3) + r;
        size_t base = (size_t)m * 1024u + n0 + (tx << 3);
#pragma unroll
        for (int c = 0; c < 8; ++c) {
            int nn = n0 + (tx << 3) + c;
            OUT[base + c] = acc[r][c] + obias[nn];
        }
    }
}

// =====================================================================
extern "C" void kernel_launch(void* const* d_in, const int* in_sizes, int n_in,
                              void* d_out, int out_size) {
    const float* x    = (const float*)d_in[0];
    const float* gmem = (const float*)d_in[1];
    const float* cw   = (const float*)d_in[2];
    const float* cb   = (const float*)d_in[3];
    const float* mw   = (const float*)d_in[4];
    const float* mb   = (const float*)d_in[5];
    const float* ow   = (const float*)d_in[6];
    const float* ob   = (const float*)d_in[7];
    float* out = (float*)d_out;

    float *pL, *pG, *pBC, *pM, *pCOMP;
    cudaGetSymbolAddress((void**)&pL,    g_L);
    cudaGetSymbolAddress((void**)&pG,    g_G);
    cudaGetSymbolAddress((void**)&pBC,   g_BC);
    cudaGetSymbolAddress((void**)&pM,    g_M);
    cudaGetSymbolAddress((void**)&pCOMP, g_COMP);

    const int BC_SMEM = 2 * 16384 * 4;       // 128 KB
    const int WA_SMEM = 20672 * 4;           // ~81 KB
    const int GA_SMEM = 24768 * 4;           // ~97 KB
    cudaFuncSetAttribute(bc_kernel, cudaFuncAttributeMaxDynamicSharedMemorySize, BC_SMEM);
    cudaFuncSetAttribute(win_attn,  cudaFuncAttributeMaxDynamicSharedMemorySize, WA_SMEM);
    cudaFuncSetAttribute(gattn,     cudaFuncAttributeMaxDynamicSharedMemorySize, GA_SMEM);

    bc_kernel  <<<dim3(256, 2), 512, BC_SMEM>>>(x, pBC);
    conv_kernel<<<64, 256>>>(x, cw, cb, pCOMP);
    win_attn   <<<dim3(8, 8, 16), 256, WA_SMEM>>>(x, pL, 0);
    win_attn   <<<dim3(8, 7, 16), 256, WA_SMEM>>>(x, pL, 1);
    norm_local <<<8192, 256>>>(pL);
    gattn      <<<dim3(128, 8, 2), 256, GA_SMEM>>>(x, gmem, pCOMP, pG);
    gemm_mix   <<<dim3(64, 8), 256>>>(pL, pG, pBC, mw, mb, pM);
    gemm_out   <<<dim3(64, 8), 256>>>(pM, ow, ob, out);
}